// round 7
// baseline (speedup 1.0000x reference)
#include <cuda_runtime.h>
#include <cstdint>

// ResRNN, int16-quantized recurrent weights, f32x2 dequant-FMA, cross-barrier
// weight prefetch (R5 base). R7: aggregator-CTA tree barrier — parallel
// release-store arrivals to per-CTA flags, CTA0 threads acquire-poll them
// (1 flag per thread), then a single release word. All sync ops morally
// strong (st.release / ld.acquire); no weak loads on the sync path.

#define T_    512
#define IND   1024
#define HD    2048
#define H2    4096
#define OUTD  1024
#define NCTA  148
#define NTHR  1024

typedef unsigned long long ull;

__device__ float g_XI[T_ * HD];
__device__ float g_A1[T_ * H2];
__device__ float g_Hs[T_ * HD];
__device__ float g_z [H2];
__device__ float g_y2[H2];
__device__ __align__(16) unsigned g_flag[NCTA] = {};
__device__ unsigned g_rel  = 0;
__device__ unsigned g_done = 0;

__device__ unsigned short g_qL1h[(size_t)H2 * HD];
__device__ unsigned short g_qL2 [(size_t)H2 * H2];
__device__ unsigned short g_qXh [(size_t)HD * H2];
__device__ float g_sL1h[H2];
__device__ float g_sL2 [H2];
__device__ float g_sXh [HD];

// ---------------------------------------------------------------------------
// fp32 GEMM:  C[M,N] = A[M,K] * B[N,K]^T + bias[N]   (64x64x16 tiles)
// ---------------------------------------------------------------------------
__global__ void __launch_bounds__(256) gemm_tt(
    const float* __restrict__ A, int lda,
    const float* __restrict__ B, int ldb,
    const float* __restrict__ bias,
    float* __restrict__ C, int ldc,
    int K)
{
    __shared__ float As[16][65];
    __shared__ float Bs[16][65];
    const int tx = threadIdx.x & 15;
    const int ty = threadIdx.x >> 4;
    const int m0 = blockIdx.y * 64;
    const int n0 = blockIdx.x * 64;

    float acc[4][4] = {};

    for (int k0 = 0; k0 < K; k0 += 16) {
#pragma unroll
        for (int i = threadIdx.x; i < 1024; i += 256) {
            int r  = i >> 4;
            int kk = i & 15;
            As[kk][r] = A[(size_t)(m0 + r) * lda + k0 + kk];
            Bs[kk][r] = B[(size_t)(n0 + r) * ldb + k0 + kk];
        }
        __syncthreads();
#pragma unroll
        for (int kk = 0; kk < 16; kk++) {
            float a[4], b[4];
#pragma unroll
            for (int i = 0; i < 4; i++) a[i] = As[kk][ty * 4 + i];
#pragma unroll
            for (int j = 0; j < 4; j++) b[j] = Bs[kk][tx * 4 + j];
#pragma unroll
            for (int i = 0; i < 4; i++)
#pragma unroll
                for (int j = 0; j < 4; j++)
                    acc[i][j] = fmaf(a[i], b[j], acc[i][j]);
        }
        __syncthreads();
    }

#pragma unroll
    for (int i = 0; i < 4; i++) {
        int m = m0 + ty * 4 + i;
#pragma unroll
        for (int j = 0; j < 4; j++) {
            int n = n0 + tx * 4 + j;
            C[(size_t)m * ldc + n] = acc[i][j] + bias[n];
        }
    }
}

// ---------------------------------------------------------------------------
// Per-row symmetric int16 quantization (deterministic; rerun each launch).
// ---------------------------------------------------------------------------
__global__ void __launch_bounds__(256) quantize_rows(
    const float* __restrict__ src, int ld, int col0, int ncols,
    unsigned short* __restrict__ dst, float* __restrict__ scales)
{
    const int r = blockIdx.x;
    const float* row = src + (size_t)r * ld + col0;
    __shared__ float red[256];

    float m = 0.f;
    for (int i = threadIdx.x; i < ncols; i += 256)
        m = fmaxf(m, fabsf(row[i]));
    red[threadIdx.x] = m;
    __syncthreads();
    for (int s = 128; s; s >>= 1) {
        if (threadIdx.x < s)
            red[threadIdx.x] = fmaxf(red[threadIdx.x], red[threadIdx.x + s]);
        __syncthreads();
    }
    const float mx  = red[0];
    const float inv = (mx > 0.f) ? 32767.0f / mx : 0.f;
    if (threadIdx.x == 0)
        scales[r] = (mx > 0.f) ? mx / 32767.0f : 1.0f;

    unsigned short* drow = dst + (size_t)r * ncols;
    for (int i = threadIdx.x; i < ncols; i += 256) {
        int q = __float2int_rn(row[i] * inv);
        drow[i] = (unsigned short)(q + 32768);
    }
}

// ---------------------------------------------------------------------------
// f32x2 helpers
// ---------------------------------------------------------------------------
__device__ __forceinline__ ull pack2(unsigned lo, unsigned hi) {
    ull r;
    asm("mov.b64 %0, {%1, %2};" : "=l"(r) : "r"(lo), "r"(hi));
    return r;
}
__device__ __forceinline__ ull add2(ull a, ull b) {
    ull r;
    asm("add.rn.f32x2 %0, %1, %2;" : "=l"(r) : "l"(a), "l"(b));
    return r;
}
__device__ __forceinline__ ull fma2(ull a, ull b, ull c) {
    ull r;
    asm("fma.rn.f32x2 %0, %1, %2, %3;" : "=l"(r) : "l"(a), "l"(b), "l"(c));
    return r;
}

__device__ __forceinline__ float warp_red(float v) {
#pragma unroll
    for (int o = 16; o; o >>= 1) v += __shfl_down_sync(0xffffffffu, v, o);
    return v;
}

// -8421376.0f (= -(2^23 + 2^15)) in both lanes
#define NMAG2 0xCB008000CB008000ull

__device__ __forceinline__ void proc8(uint4 w, int i,
                                      const ulonglong2* __restrict__ x2,
                                      ull& a0, ull& a1)
{
    int sw = (i >> 2) & 7;
    ulonglong2 X0 = x2[(2 * i) ^ sw];
    ulonglong2 X1 = x2[(2 * i) ^ sw ^ 1];
    a0 = fma2(add2(pack2(__byte_perm(w.x, 0x4B000000u, 0x7410),
                         __byte_perm(w.x, 0x4B000000u, 0x7432)), NMAG2),
              X0.x, a0);
    a1 = fma2(add2(pack2(__byte_perm(w.y, 0x4B000000u, 0x7410),
                         __byte_perm(w.y, 0x4B000000u, 0x7432)), NMAG2),
              X0.y, a1);
    a0 = fma2(add2(pack2(__byte_perm(w.z, 0x4B000000u, 0x7410),
                         __byte_perm(w.z, 0x4B000000u, 0x7432)), NMAG2),
              X1.x, a0);
    a1 = fma2(add2(pack2(__byte_perm(w.w, 0x4B000000u, 0x7410),
                         __byte_perm(w.w, 0x4B000000u, 0x7432)), NMAG2),
              X1.y, a1);
}

template <int N16>
__device__ __forceinline__ float dotq2(const uint4* __restrict__ qrow,
                                       const float4* __restrict__ xs,
                                       int lane, uint4 pf0, uint4 pf1)
{
    const ulonglong2* x2 = reinterpret_cast<const ulonglong2*>(xs);
    ull a0 = 0, a1 = 0;
    proc8(pf0, lane,      x2, a0, a1);
    proc8(pf1, lane + 32, x2, a0, a1);
#pragma unroll 4
    for (int k = 2; k < N16 / 32; k++) {
        int i = lane + 32 * k;
        uint4 w = __ldcg(qrow + i);
        proc8(w, i, x2, a0, a1);
    }
    a0 = add2(a0, a1);
    unsigned lo, hi;
    asm("mov.b64 {%0, %1}, %2;" : "=r"(lo), "=r"(hi) : "l"(a0));
    return warp_red(__uint_as_float(lo) + __uint_as_float(hi));
}

// ---------------------------------------------------------------------------
// Aggregator-CTA tree barrier (all sync ops morally strong).
//   CTA j>0, tid0 : st.release g_flag[j]=ep;  acquire-poll g_rel >= ep
//   CTA 0, tid 1..147: acquire-poll g_flag[tid] >= ep  (parallel, distinct)
//   CTA 0, tid 0 (after syncthreads): st.release g_rel = ep
// ---------------------------------------------------------------------------
#define GRID_SYNC() do {                                                      \
    __syncthreads();                                                          \
    ep++;                                                                     \
    if (bid == 0) {                                                           \
        if (tid > 0 && tid < NCTA) {                                          \
            unsigned v;                                                       \
            do {                                                              \
                asm volatile("ld.acquire.gpu.global.u32 %0, [%1];"            \
                             : "=r"(v) : "l"(&g_flag[tid]));                  \
            } while (v < ep);                                                 \
        }                                                                     \
        __syncthreads();                                                      \
        if (tid == 0)                                                         \
            asm volatile("st.release.gpu.global.u32 [%0], %1;"                \
                         :: "l"(&g_rel), "r"(ep) : "memory");                 \
    } else {                                                                  \
        if (tid == 0) {                                                       \
            asm volatile("st.release.gpu.global.u32 [%0], %1;"                \
                         :: "l"(&g_flag[bid]), "r"(ep) : "memory");           \
            unsigned v;                                                       \
            while (1) {                                                       \
                asm volatile("ld.acquire.gpu.global.u32 %0, [%1];"            \
                             : "=r"(v) : "l"(&g_rel));                        \
                if (v >= ep) break;                                           \
                __nanosleep(32);                                              \
            }                                                                 \
        }                                                                     \
        __syncthreads();                                                      \
    }                                                                         \
} while (0)

__global__ void __launch_bounds__(NTHR, 1) resrnn_seq(
    const float* __restrict__ h0,
    const float* __restrict__ l2b,
    const float* __restrict__ xh2hb)
{
    __shared__ float4 hs4[HD / 4];   //  8 KB: h_prev, swizzled
    __shared__ float4 sb4[H2 / 4];   // 16 KB: phase input vector, swizzled
    const int tid  = threadIdx.x;
    const int wid  = tid >> 5;
    const int lane = tid & 31;
    const int bid  = blockIdx.x;
    const int r    = bid + NCTA * wid;   // this warp's output row
    unsigned  ep   = 0;

    const uint4* qA = reinterpret_cast<const uint4*>(
        g_qL1h + (size_t)(r < H2 ? r : 0) * HD);
    const uint4* qB = reinterpret_cast<const uint4*>(
        g_qL2 + (size_t)(r < H2 ? r : 0) * H2);
    const uint4* qC = reinterpret_cast<const uint4*>(
        g_qXh + (size_t)(r < HD ? r : 0) * H2);

    // initial prefetch: phase A of step 0
    uint4 pf0 = {0,0,0,0}, pf1 = {0,0,0,0};
    if (r < H2) { pf0 = __ldcg(qA + lane); pf1 = __ldcg(qA + lane + 32); }

    for (int t = 0; t < T_; t++) {
        const float4* hprev4 = (t == 0)
            ? reinterpret_cast<const float4*>(h0)
            : reinterpret_cast<const float4*>(&g_Hs[(size_t)(t - 1) * HD]);

        // ---- stage h_prev (swizzled) ----
        for (int j = tid; j < HD / 4; j += NTHR)
            hs4[j ^ ((j >> 3) & 7)] = __ldcg(hprev4 + j);
        __syncthreads();

        // ---- Phase A: z = relu(A1[t] + l1h @ h) ----
        if (r < H2) {
            float s = dotq2<HD / 8>(qA, hs4, lane, pf0, pf1);
            if (lane == 0) {
                float zz = __ldcg(&g_A1[(size_t)t * H2 + r]) + g_sL1h[r] * s;
                g_z[r] = fmaxf(zz, 0.f);
            }
        }
        if (r < H2) { pf0 = __ldcg(qB + lane); pf1 = __ldcg(qB + lane + 32); }
        GRID_SYNC();

        // ---- Phase B: y2 = l2 @ z + l2_b ----
        {
            const float4* z4 = reinterpret_cast<const float4*>(g_z);
            for (int j = tid; j < H2 / 4; j += NTHR)
                sb4[j ^ ((j >> 3) & 7)] = __ldcg(z4 + j);
        }
        __syncthreads();
        if (r < H2) {
            float s = dotq2<H2 / 8>(qB, sb4, lane, pf0, pf1);
            if (lane == 0) g_y2[r] = g_sL2[r] * s + __ldcg(l2b + r);
        }
        if (r < HD) { pf0 = __ldcg(qC + lane); pf1 = __ldcg(qC + lane + 32); }
        GRID_SYNC();

        // ---- Phase C: temp = relu(xh + y2); h' = xh2h @ temp + b ----
        {
            const float4* xi4 = reinterpret_cast<const float4*>(
                &g_XI[(size_t)t * HD]);
            const float4* y4 = reinterpret_cast<const float4*>(g_y2);
            for (int j = tid; j < H2 / 4; j += NTHR) {
                float4 xh;
                if (j < HD / 4) {
                    xh = __ldcg(xi4 + j);
                } else {
                    int jj = j - HD / 4;
                    xh = hs4[jj ^ ((jj >> 3) & 7)];   // unswizzle h
                }
                float4 y = __ldcg(y4 + j);
                float4 tv;
                tv.x = fmaxf(xh.x + y.x, 0.f);
                tv.y = fmaxf(xh.y + y.y, 0.f);
                tv.z = fmaxf(xh.z + y.z, 0.f);
                tv.w = fmaxf(xh.w + y.w, 0.f);
                sb4[j ^ ((j >> 3) & 7)] = tv;
            }
        }
        __syncthreads();
        if (r < HD) {
            float s = dotq2<H2 / 8>(qC, sb4, lane, pf0, pf1);
            if (lane == 0)
                g_Hs[(size_t)t * HD + r] = g_sXh[r] * s + __ldcg(xh2hb + r);
        }
        if (r < H2) { pf0 = __ldcg(qA + lane); pf1 = __ldcg(qA + lane + 32); }
        GRID_SYNC();
    }

    // Reset barrier state for next graph replay. Handshake: every CTA's tid0
    // signals done; CTA0 (sole writer afterwards) clears all words.
    if (tid == 0) {
        __threadfence();
        atomicAdd(&g_done, 1u);
        if (bid == 0) {
            unsigned v;
            while (1) {
                asm volatile("ld.global.acquire.gpu.u32 %0, [%1];"
                             : "=r"(v) : "l"(&g_done));
                if (v >= (unsigned)NCTA) break;
                __nanosleep(64);
            }
            for (int q = 0; q < NCTA; q++) g_flag[q] = 0u;
            g_rel  = 0u;
            g_done = 0u;
            __threadfence();
        }
    }
}

__global__ void copy_hfinal(float* __restrict__ out)
{
    int i = blockIdx.x * blockDim.x + threadIdx.x;
    if (i < HD) out[i] = g_Hs[(size_t)(T_ - 1) * HD + i];
}

// ---------------------------------------------------------------------------
extern "C" void kernel_launch(void* const* d_in, const int* in_sizes, int n_in,
                              void* d_out, int out_size)
{
    const float* x      = (const float*)d_in[0];
    const float* h0     = (const float*)d_in[1];
    const float* inp_w  = (const float*)d_in[2];
    const float* inp_b  = (const float*)d_in[3];
    const float* l1_w   = (const float*)d_in[4];
    const float* l1_b   = (const float*)d_in[5];
    const float* l2_w   = (const float*)d_in[6];
    const float* l2_b   = (const float*)d_in[7];
    const float* xh2h_w = (const float*)d_in[8];
    const float* xh2h_b = (const float*)d_in[9];
    const float* out_w  = (const float*)d_in[10];
    const float* out_b  = (const float*)d_in[11];

    float *pXI, *pA1, *pHs, *pSL1h, *pSL2, *pSXh;
    unsigned short *pQL1h, *pQL2, *pQXh;
    cudaGetSymbolAddress((void**)&pXI,   g_XI);
    cudaGetSymbolAddress((void**)&pA1,   g_A1);
    cudaGetSymbolAddress((void**)&pHs,   g_Hs);
    cudaGetSymbolAddress((void**)&pQL1h, g_qL1h);
    cudaGetSymbolAddress((void**)&pQL2,  g_qL2);
    cudaGetSymbolAddress((void**)&pQXh,  g_qXh);
    cudaGetSymbolAddress((void**)&pSL1h, g_sL1h);
    cudaGetSymbolAddress((void**)&pSL2,  g_sL2);
    cudaGetSymbolAddress((void**)&pSXh,  g_sXh);

    // Quantize recurrent weights (int16 + per-row scale)
    quantize_rows<<<H2, 256>>>(l1_w,   H2, HD, HD, pQL1h, pSL1h);
    quantize_rows<<<H2, 256>>>(l2_w,   H2, 0,  H2, pQL2,  pSL2);
    quantize_rows<<<HD, 256>>>(xh2h_w, H2, 0,  H2, pQXh,  pSXh);

    // K1: XI[512,2048] = x * inp_w^T + inp_b
    gemm_tt<<<dim3(HD / 64, T_ / 64), 256>>>(x, IND, inp_w, IND, inp_b,
                                             pXI, HD, IND);
    // K2: A1[512,4096] = XI * l1_w[:, :2048]^T + l1_b
    gemm_tt<<<dim3(H2 / 64, T_ / 64), 256>>>(pXI, HD, l1_w, H2, l1_b,
                                             pA1, H2, HD);
    // Sequential recurrence
    resrnn_seq<<<NCTA, NTHR>>>(h0, l2_b, xh2h_b);

    // K3: ys[512,1024] = Hs * out_w^T + out_b
    gemm_tt<<<dim3(OUTD / 64, T_ / 64), 256>>>(pHs, HD, out_w, HD, out_b,
                                               (float*)d_out, OUTD, HD);

    if (out_size >= T_ * OUTD + HD) {
        copy_hfinal<<<2, NTHR>>>((float*)d_out + (size_t)T_ * OUTD);
    }
}

// round 8
// speedup vs baseline: 1.2199x; 1.2199x over previous
#include <cuda_runtime.h>
#include <cstdint>

// ResRNN, int16-quantized recurrent weights, f32x2 dequant-FMA, cross-barrier
// weight prefetch (R5 base, R2 barrier). R8: prefetch depth 4 for phases B/C;
// quantize merged into one kernel and launch order set so resrnn_seq is the
// 4th kernel launch (ncu -s 5 with 2 harness pre-launches captures it).

#define T_    512
#define IND   1024
#define HD    2048
#define H2    4096
#define OUTD  1024
#define NCTA  148
#define NTHR  1024

typedef unsigned long long ull;

__device__ float g_XI[T_ * HD];
__device__ float g_A1[T_ * H2];
__device__ float g_Hs[T_ * HD];
__device__ float g_z [H2];
__device__ float g_y2[H2];
__device__ unsigned g_bar  = 0;
__device__ unsigned g_done = 0;

__device__ unsigned short g_qL1h[(size_t)H2 * HD];
__device__ unsigned short g_qL2 [(size_t)H2 * H2];
__device__ unsigned short g_qXh [(size_t)HD * H2];
__device__ float g_sL1h[H2];
__device__ float g_sL2 [H2];
__device__ float g_sXh [HD];

// ---------------------------------------------------------------------------
// fp32 GEMM:  C[M,N] = A[M,K] * B[N,K]^T + bias[N]   (64x64x16 tiles)
// ---------------------------------------------------------------------------
__global__ void __launch_bounds__(256) gemm_tt(
    const float* __restrict__ A, int lda,
    const float* __restrict__ B, int ldb,
    const float* __restrict__ bias,
    float* __restrict__ C, int ldc,
    int K)
{
    __shared__ float As[16][65];
    __shared__ float Bs[16][65];
    const int tx = threadIdx.x & 15;
    const int ty = threadIdx.x >> 4;
    const int m0 = blockIdx.y * 64;
    const int n0 = blockIdx.x * 64;

    float acc[4][4] = {};

    for (int k0 = 0; k0 < K; k0 += 16) {
#pragma unroll
        for (int i = threadIdx.x; i < 1024; i += 256) {
            int r  = i >> 4;
            int kk = i & 15;
            As[kk][r] = A[(size_t)(m0 + r) * lda + k0 + kk];
            Bs[kk][r] = B[(size_t)(n0 + r) * ldb + k0 + kk];
        }
        __syncthreads();
#pragma unroll
        for (int kk = 0; kk < 16; kk++) {
            float a[4], b[4];
#pragma unroll
            for (int i = 0; i < 4; i++) a[i] = As[kk][ty * 4 + i];
#pragma unroll
            for (int j = 0; j < 4; j++) b[j] = Bs[kk][tx * 4 + j];
#pragma unroll
            for (int i = 0; i < 4; i++)
#pragma unroll
                for (int j = 0; j < 4; j++)
                    acc[i][j] = fmaf(a[i], b[j], acc[i][j]);
        }
        __syncthreads();
    }

#pragma unroll
    for (int i = 0; i < 4; i++) {
        int m = m0 + ty * 4 + i;
#pragma unroll
        for (int j = 0; j < 4; j++) {
            int n = n0 + tx * 4 + j;
            C[(size_t)m * ldc + n] = acc[i][j] + bias[n];
        }
    }
}

// ---------------------------------------------------------------------------
// Merged per-row int16 quantization for all three recurrent matrices.
// grid.x = 4096 (l1h) + 4096 (l2) + 2048 (xh2h) = 10240 blocks.
// ---------------------------------------------------------------------------
__global__ void __launch_bounds__(256) quantize_all(
    const float* __restrict__ l1_w,
    const float* __restrict__ l2_w,
    const float* __restrict__ xh2h_w)
{
    const int b = blockIdx.x;
    const float* src; int r, ld, col0, ncols;
    unsigned short* dst; float* scales;
    if (b < H2) {
        r = b;          src = l1_w;   ld = H2; col0 = HD; ncols = HD;
        dst = g_qL1h;   scales = g_sL1h;
    } else if (b < 2 * H2) {
        r = b - H2;     src = l2_w;   ld = H2; col0 = 0;  ncols = H2;
        dst = g_qL2;    scales = g_sL2;
    } else {
        r = b - 2 * H2; src = xh2h_w; ld = H2; col0 = 0;  ncols = H2;
        dst = g_qXh;    scales = g_sXh;
    }

    const float* row = src + (size_t)r * ld + col0;
    __shared__ float red[256];

    float m = 0.f;
    for (int i = threadIdx.x; i < ncols; i += 256)
        m = fmaxf(m, fabsf(row[i]));
    red[threadIdx.x] = m;
    __syncthreads();
    for (int s = 128; s; s >>= 1) {
        if (threadIdx.x < s)
            red[threadIdx.x] = fmaxf(red[threadIdx.x], red[threadIdx.x + s]);
        __syncthreads();
    }
    const float mx  = red[0];
    const float inv = (mx > 0.f) ? 32767.0f / mx : 0.f;
    if (threadIdx.x == 0)
        scales[r] = (mx > 0.f) ? mx / 32767.0f : 1.0f;

    unsigned short* drow = dst + (size_t)r * ncols;
    for (int i = threadIdx.x; i < ncols; i += 256) {
        int q = __float2int_rn(row[i] * inv);
        drow[i] = (unsigned short)(q + 32768);
    }
}

// ---------------------------------------------------------------------------
// f32x2 helpers
// ---------------------------------------------------------------------------
__device__ __forceinline__ ull pack2(unsigned lo, unsigned hi) {
    ull r;
    asm("mov.b64 %0, {%1, %2};" : "=l"(r) : "r"(lo), "r"(hi));
    return r;
}
__device__ __forceinline__ ull add2(ull a, ull b) {
    ull r;
    asm("add.rn.f32x2 %0, %1, %2;" : "=l"(r) : "l"(a), "l"(b));
    return r;
}
__device__ __forceinline__ ull fma2(ull a, ull b, ull c) {
    ull r;
    asm("fma.rn.f32x2 %0, %1, %2, %3;" : "=l"(r) : "l"(a), "l"(b), "l"(c));
    return r;
}

__device__ __forceinline__ float warp_red(float v) {
#pragma unroll
    for (int o = 16; o; o >>= 1) v += __shfl_down_sync(0xffffffffu, v, o);
    return v;
}

// -8421376.0f (= -(2^23 + 2^15)) in both lanes
#define NMAG2 0xCB008000CB008000ull

__device__ __forceinline__ void proc8(uint4 w, int i,
                                      const ulonglong2* __restrict__ x2,
                                      ull& a0, ull& a1)
{
    int sw = (i >> 2) & 7;
    ulonglong2 X0 = x2[(2 * i) ^ sw];
    ulonglong2 X1 = x2[(2 * i) ^ sw ^ 1];
    a0 = fma2(add2(pack2(__byte_perm(w.x, 0x4B000000u, 0x7410),
                         __byte_perm(w.x, 0x4B000000u, 0x7432)), NMAG2),
              X0.x, a0);
    a1 = fma2(add2(pack2(__byte_perm(w.y, 0x4B000000u, 0x7410),
                         __byte_perm(w.y, 0x4B000000u, 0x7432)), NMAG2),
              X0.y, a1);
    a0 = fma2(add2(pack2(__byte_perm(w.z, 0x4B000000u, 0x7410),
                         __byte_perm(w.z, 0x4B000000u, 0x7432)), NMAG2),
              X1.x, a0);
    a1 = fma2(add2(pack2(__byte_perm(w.w, 0x4B000000u, 0x7410),
                         __byte_perm(w.w, 0x4B000000u, 0x7432)), NMAG2),
              X1.y, a1);
}

// dequant-dot: N16 uint4s per row; first NPF uint4s arrive prefetched
// (loaded before the previous grid barrier), rest stream with ld.cg.
template <int N16, int NPF>
__device__ __forceinline__ float dotqP(const uint4* __restrict__ qrow,
                                       const float4* __restrict__ xs,
                                       int lane, const uint4* pf)
{
    const ulonglong2* x2 = reinterpret_cast<const ulonglong2*>(xs);
    ull a0 = 0, a1 = 0;
#pragma unroll
    for (int k = 0; k < NPF; k++)
        proc8(pf[k], lane + 32 * k, x2, a0, a1);
#pragma unroll 4
    for (int k = NPF; k < N16 / 32; k++) {
        int i = lane + 32 * k;
        uint4 w = __ldcg(qrow + i);
        proc8(w, i, x2, a0, a1);
    }
    a0 = add2(a0, a1);
    unsigned lo, hi;
    asm("mov.b64 {%0, %1}, %2;" : "=r"(lo), "=r"(hi) : "l"(a0));
    return warp_red(__uint_as_float(lo) + __uint_as_float(hi));
}

// R2 barrier, unchanged (best measured).
#define GRID_SYNC() do {                                                      \
    __syncthreads();                                                          \
    if (tid == 0) {                                                           \
        __threadfence();                                                      \
        atomicAdd(&g_bar, 1u);                                                \
        ep++;                                                                 \
        unsigned tgt = ep * (unsigned)NCTA;                                   \
        unsigned v;                                                           \
        while (1) {                                                           \
            asm volatile("ld.global.acquire.gpu.u32 %0, [%1];"                \
                         : "=r"(v) : "l"(&g_bar));                            \
            if (v >= tgt) break;                                              \
            __nanosleep(32);                                                  \
        }                                                                     \
    }                                                                         \
    __syncthreads();                                                          \
} while (0)

__global__ void __launch_bounds__(NTHR, 1) resrnn_seq(
    const float* __restrict__ h0,
    const float* __restrict__ l2b,
    const float* __restrict__ xh2hb)
{
    __shared__ float4 hs4[HD / 4];   //  8 KB: h_prev, swizzled
    __shared__ float4 sb4[H2 / 4];   // 16 KB: phase input vector, swizzled
    const int tid  = threadIdx.x;
    const int wid  = tid >> 5;
    const int lane = tid & 31;
    const int bid  = blockIdx.x;
    const int r    = bid + NCTA * wid;   // this warp's output row
    unsigned  ep   = 0;

    const uint4* qA = reinterpret_cast<const uint4*>(
        g_qL1h + (size_t)(r < H2 ? r : 0) * HD);
    const uint4* qB = reinterpret_cast<const uint4*>(
        g_qL2 + (size_t)(r < H2 ? r : 0) * H2);
    const uint4* qC = reinterpret_cast<const uint4*>(
        g_qXh + (size_t)(r < HD ? r : 0) * H2);

    uint4 pf[4];
    pf[0] = make_uint4(0, 0, 0, 0); pf[1] = pf[0];
    pf[2] = pf[0]; pf[3] = pf[0];
    // initial prefetch: phase A of step 0 (2 groups)
    if (r < H2) {
        pf[0] = __ldcg(qA + lane);
        pf[1] = __ldcg(qA + lane + 32);
    }

    for (int t = 0; t < T_; t++) {
        const float4* hprev4 = (t == 0)
            ? reinterpret_cast<const float4*>(h0)
            : reinterpret_cast<const float4*>(&g_Hs[(size_t)(t - 1) * HD]);

        // ---- stage h_prev (swizzled) ----
        for (int j = tid; j < HD / 4; j += NTHR)
            hs4[j ^ ((j >> 3) & 7)] = __ldcg(hprev4 + j);
        __syncthreads();

        // ---- Phase A: z = relu(A1[t] + l1h @ h) ----
        if (r < H2) {
            float s = dotqP<HD / 8, 2>(qA, hs4, lane, pf);
            if (lane == 0) {
                float zz = __ldcg(&g_A1[(size_t)t * H2 + r]) + g_sL1h[r] * s;
                g_z[r] = fmaxf(zz, 0.f);
            }
        }
        // prefetch phase-B weights (4 groups) across the barrier
        if (r < H2) {
#pragma unroll
            for (int k = 0; k < 4; k++) pf[k] = __ldcg(qB + lane + 32 * k);
        }
        GRID_SYNC();

        // ---- Phase B: y2 = l2 @ z + l2_b ----
        {
            const float4* z4 = reinterpret_cast<const float4*>(g_z);
            for (int j = tid; j < H2 / 4; j += NTHR)
                sb4[j ^ ((j >> 3) & 7)] = __ldcg(z4 + j);
        }
        __syncthreads();
        if (r < H2) {
            float s = dotqP<H2 / 8, 4>(qB, sb4, lane, pf);
            if (lane == 0) g_y2[r] = g_sL2[r] * s + __ldcg(l2b + r);
        }
        // prefetch phase-C weights (4 groups) across the barrier
        if (r < HD) {
#pragma unroll
            for (int k = 0; k < 4; k++) pf[k] = __ldcg(qC + lane + 32 * k);
        }
        GRID_SYNC();

        // ---- Phase C: temp = relu(xh + y2); h' = xh2h @ temp + b ----
        {
            const float4* xi4 = reinterpret_cast<const float4*>(
                &g_XI[(size_t)t * HD]);
            const float4* y4 = reinterpret_cast<const float4*>(g_y2);
            for (int j = tid; j < H2 / 4; j += NTHR) {
                float4 xh;
                if (j < HD / 4) {
                    xh = __ldcg(xi4 + j);
                } else {
                    int jj = j - HD / 4;
                    xh = hs4[jj ^ ((jj >> 3) & 7)];   // unswizzle h
                }
                float4 y = __ldcg(y4 + j);
                float4 tv;
                tv.x = fmaxf(xh.x + y.x, 0.f);
                tv.y = fmaxf(xh.y + y.y, 0.f);
                tv.z = fmaxf(xh.z + y.z, 0.f);
                tv.w = fmaxf(xh.w + y.w, 0.f);
                sb4[j ^ ((j >> 3) & 7)] = tv;
            }
        }
        __syncthreads();
        if (r < HD) {
            float s = dotqP<H2 / 8, 4>(qC, sb4, lane, pf);
            if (lane == 0)
                g_Hs[(size_t)t * HD + r] = g_sXh[r] * s + __ldcg(xh2hb + r);
        }
        // prefetch next step's phase-A weights (2 groups) across the barrier
        if (r < H2) {
            pf[0] = __ldcg(qA + lane);
            pf[1] = __ldcg(qA + lane + 32);
        }
        GRID_SYNC();
    }

    // Reset barrier for next graph replay (handshake: nobody still spinning).
    if (tid == 0) {
        __threadfence();
        atomicAdd(&g_done, 1u);
        if (bid == 0) {
            unsigned v;
            while (1) {
                asm volatile("ld.global.acquire.gpu.u32 %0, [%1];"
                             : "=r"(v) : "l"(&g_done));
                if (v >= (unsigned)NCTA) break;
                __nanosleep(64);
            }
            g_bar  = 0u;
            g_done = 0u;
            __threadfence();
        }
    }
}

__global__ void copy_hfinal(float* __restrict__ out)
{
    int i = blockIdx.x * blockDim.x + threadIdx.x;
    if (i < HD) out[i] = g_Hs[(size_t)(T_ - 1) * HD + i];
}

// ---------------------------------------------------------------------------
extern "C" void kernel_launch(void* const* d_in, const int* in_sizes, int n_in,
                              void* d_out, int out_size)
{
    const float* x      = (const float*)d_in[0];
    const float* h0     = (const float*)d_in[1];
    const float* inp_w  = (const float*)d_in[2];
    const float* inp_b  = (const float*)d_in[3];
    const float* l1_w   = (const float*)d_in[4];
    const float* l1_b   = (const float*)d_in[5];
    const float* l2_w   = (const float*)d_in[6];
    const float* l2_b   = (const float*)d_in[7];
    const float* xh2h_w = (const float*)d_in[8];
    const float* xh2h_b = (const float*)d_in[9];
    const float* out_w  = (const float*)d_in[10];
    const float* out_b  = (const float*)d_in[11];

    float *pXI, *pA1, *pHs;
    cudaGetSymbolAddress((void**)&pXI, g_XI);
    cudaGetSymbolAddress((void**)&pA1, g_A1);
    cudaGetSymbolAddress((void**)&pHs, g_Hs);

    // Launch order chosen so resrnn_seq is the 4th launch (ncu -s 5 with the
    // harness's 2 pre-launches then captures it).
    // K1: XI[512,2048] = x * inp_w^T + inp_b      (uses fp32 weights)
    gemm_tt<<<dim3(HD / 64, T_ / 64), 256>>>(x, IND, inp_w, IND, inp_b,
                                             pXI, HD, IND);
    // K2: A1[512,4096] = XI * l1_w[:, :2048]^T + l1_b
    gemm_tt<<<dim3(H2 / 64, T_ / 64), 256>>>(pXI, HD, l1_w, H2, l1_b,
                                             pA1, H2, HD);
    // Quantize all recurrent weights in one launch
    quantize_all<<<2 * H2 + HD, 256>>>(l1_w, l2_w, xh2h_w);

    // Sequential recurrence
    resrnn_seq<<<NCTA, NTHR>>>(h0, l2_b, xh2h_b);

    // K3: ys[512,1024] = Hs * out_w^T + out_b
    gemm_tt<<<dim3(OUTD / 64, T_ / 64), 256>>>(pHs, HD, out_w, HD, out_b,
                                               (float*)d_out, OUTD, HD);

    if (out_size >= T_ * OUTD + HD) {
        copy_hfinal<<<2, NTHR>>>((float*)d_out + (size_t)T_ * OUTD);
    }
}

// round 9
// speedup vs baseline: 1.2212x; 1.0011x over previous
#include <cuda_runtime.h>
#include <cstdint>

// ResRNN, int16-quantized recurrent weights, f32x2 dequant-FMA, cross-barrier
// weight prefetch, R2 grid barrier. R9: each warp computes TWO adjacent rows,
// sharing the shared-memory x reads between them (halves LDS traffic through
// L1tex, which ncu R8 showed as the top pipe at 47%).

#define T_    512
#define IND   1024
#define HD    2048
#define H2    4096
#define OUTD  1024
#define NCTA  148
#define NTHR  1024

typedef unsigned long long ull;

__device__ float g_XI[T_ * HD];
__device__ float g_A1[T_ * H2];
__device__ float g_Hs[T_ * HD];
__device__ float g_z [H2];
__device__ float g_y2[H2];
__device__ unsigned g_bar  = 0;
__device__ unsigned g_done = 0;

__device__ unsigned short g_qL1h[(size_t)H2 * HD];
__device__ unsigned short g_qL2 [(size_t)H2 * H2];
__device__ unsigned short g_qXh [(size_t)HD * H2];
__device__ float g_sL1h[H2];
__device__ float g_sL2 [H2];
__device__ float g_sXh [HD];

// ---------------------------------------------------------------------------
// fp32 GEMM:  C[M,N] = A[M,K] * B[N,K]^T + bias[N]   (64x64x16 tiles)
// ---------------------------------------------------------------------------
__global__ void __launch_bounds__(256) gemm_tt(
    const float* __restrict__ A, int lda,
    const float* __restrict__ B, int ldb,
    const float* __restrict__ bias,
    float* __restrict__ C, int ldc,
    int K)
{
    __shared__ float As[16][65];
    __shared__ float Bs[16][65];
    const int tx = threadIdx.x & 15;
    const int ty = threadIdx.x >> 4;
    const int m0 = blockIdx.y * 64;
    const int n0 = blockIdx.x * 64;

    float acc[4][4] = {};

    for (int k0 = 0; k0 < K; k0 += 16) {
#pragma unroll
        for (int i = threadIdx.x; i < 1024; i += 256) {
            int r  = i >> 4;
            int kk = i & 15;
            As[kk][r] = A[(size_t)(m0 + r) * lda + k0 + kk];
            Bs[kk][r] = B[(size_t)(n0 + r) * ldb + k0 + kk];
        }
        __syncthreads();
#pragma unroll
        for (int kk = 0; kk < 16; kk++) {
            float a[4], b[4];
#pragma unroll
            for (int i = 0; i < 4; i++) a[i] = As[kk][ty * 4 + i];
#pragma unroll
            for (int j = 0; j < 4; j++) b[j] = Bs[kk][tx * 4 + j];
#pragma unroll
            for (int i = 0; i < 4; i++)
#pragma unroll
                for (int j = 0; j < 4; j++)
                    acc[i][j] = fmaf(a[i], b[j], acc[i][j]);
        }
        __syncthreads();
    }

#pragma unroll
    for (int i = 0; i < 4; i++) {
        int m = m0 + ty * 4 + i;
#pragma unroll
        for (int j = 0; j < 4; j++) {
            int n = n0 + tx * 4 + j;
            C[(size_t)m * ldc + n] = acc[i][j] + bias[n];
        }
    }
}

// ---------------------------------------------------------------------------
// Merged per-row int16 quantization for all three recurrent matrices.
// ---------------------------------------------------------------------------
__global__ void __launch_bounds__(256) quantize_all(
    const float* __restrict__ l1_w,
    const float* __restrict__ l2_w,
    const float* __restrict__ xh2h_w)
{
    const int b = blockIdx.x;
    const float* src; int r, ld, col0, ncols;
    unsigned short* dst; float* scales;
    if (b < H2) {
        r = b;          src = l1_w;   ld = H2; col0 = HD; ncols = HD;
        dst = g_qL1h;   scales = g_sL1h;
    } else if (b < 2 * H2) {
        r = b - H2;     src = l2_w;   ld = H2; col0 = 0;  ncols = H2;
        dst = g_qL2;    scales = g_sL2;
    } else {
        r = b - 2 * H2; src = xh2h_w; ld = H2; col0 = 0;  ncols = H2;
        dst = g_qXh;    scales = g_sXh;
    }

    const float* row = src + (size_t)r * ld + col0;
    __shared__ float red[256];

    float m = 0.f;
    for (int i = threadIdx.x; i < ncols; i += 256)
        m = fmaxf(m, fabsf(row[i]));
    red[threadIdx.x] = m;
    __syncthreads();
    for (int s = 128; s; s >>= 1) {
        if (threadIdx.x < s)
            red[threadIdx.x] = fmaxf(red[threadIdx.x], red[threadIdx.x + s]);
        __syncthreads();
    }
    const float mx  = red[0];
    const float inv = (mx > 0.f) ? 32767.0f / mx : 0.f;
    if (threadIdx.x == 0)
        scales[r] = (mx > 0.f) ? mx / 32767.0f : 1.0f;

    unsigned short* drow = dst + (size_t)r * ncols;
    for (int i = threadIdx.x; i < ncols; i += 256) {
        int q = __float2int_rn(row[i] * inv);
        drow[i] = (unsigned short)(q + 32768);
    }
}

// ---------------------------------------------------------------------------
// f32x2 helpers
// ---------------------------------------------------------------------------
__device__ __forceinline__ ull pack2(unsigned lo, unsigned hi) {
    ull r;
    asm("mov.b64 %0, {%1, %2};" : "=l"(r) : "r"(lo), "r"(hi));
    return r;
}
__device__ __forceinline__ ull add2(ull a, ull b) {
    ull r;
    asm("add.rn.f32x2 %0, %1, %2;" : "=l"(r) : "l"(a), "l"(b));
    return r;
}
__device__ __forceinline__ ull fma2(ull a, ull b, ull c) {
    ull r;
    asm("fma.rn.f32x2 %0, %1, %2, %3;" : "=l"(r) : "l"(a), "l"(b), "l"(c));
    return r;
}

__device__ __forceinline__ float warp_red(float v) {
#pragma unroll
    for (int o = 16; o; o >>= 1) v += __shfl_down_sync(0xffffffffu, v, o);
    return v;
}

// -8421376.0f (= -(2^23 + 2^15)) in both lanes
#define NMAG2 0xCB008000CB008000ull

// dequant 2 biased-u16 (packed in u32) -> f32x2
__device__ __forceinline__ ull dq(unsigned u) {
    return add2(pack2(__byte_perm(u, 0x4B000000u, 0x7410),
                      __byte_perm(u, 0x4B000000u, 0x7432)), NMAG2);
}

// process one 16B weight group for TWO rows, sharing the x loads.
__device__ __forceinline__ void proc8p(uint4 w0, uint4 w1, int i,
                                       const ulonglong2* __restrict__ x2,
                                       ull& a00, ull& a01,
                                       ull& a10, ull& a11)
{
    int sw = (i >> 2) & 7;
    ulonglong2 X0 = x2[(2 * i) ^ sw];
    ulonglong2 X1 = x2[(2 * i) ^ sw ^ 1];
    a00 = fma2(dq(w0.x), X0.x, a00);
    a01 = fma2(dq(w0.y), X0.y, a01);
    a10 = fma2(dq(w1.x), X0.x, a10);
    a11 = fma2(dq(w1.y), X0.y, a11);
    a00 = fma2(dq(w0.z), X1.x, a00);
    a01 = fma2(dq(w0.w), X1.y, a01);
    a10 = fma2(dq(w1.z), X1.x, a10);
    a11 = fma2(dq(w1.w), X1.y, a11);
}

// paired dequant-dot: rows q0,q1 of N16 uint4s vs swizzled shared x.
// First group of each row arrives prefetched (loaded before the barrier).
template <int N16>
__device__ __forceinline__ float2 dotq_pair(
    const uint4* __restrict__ q0, const uint4* __restrict__ q1,
    const float4* __restrict__ xs, int lane, uint4 pf0, uint4 pf1)
{
    const ulonglong2* x2 = reinterpret_cast<const ulonglong2*>(xs);
    ull a00 = 0, a01 = 0, a10 = 0, a11 = 0;
    proc8p(pf0, pf1, lane, x2, a00, a01, a10, a11);
#pragma unroll 4
    for (int k = 1; k < N16 / 32; k++) {
        int i = lane + 32 * k;
        uint4 w0 = __ldcg(q0 + i);
        uint4 w1 = __ldcg(q1 + i);
        proc8p(w0, w1, i, x2, a00, a01, a10, a11);
    }
    a00 = add2(a00, a01);
    a10 = add2(a10, a11);
    unsigned lo, hi;
    float2 s;
    asm("mov.b64 {%0, %1}, %2;" : "=r"(lo), "=r"(hi) : "l"(a00));
    s.x = warp_red(__uint_as_float(lo) + __uint_as_float(hi));
    asm("mov.b64 {%0, %1}, %2;" : "=r"(lo), "=r"(hi) : "l"(a10));
    s.y = warp_red(__uint_as_float(lo) + __uint_as_float(hi));
    return s;
}

// R2 barrier, unchanged (best measured).
#define GRID_SYNC() do {                                                      \
    __syncthreads();                                                          \
    if (tid == 0) {                                                           \
        __threadfence();                                                      \
        atomicAdd(&g_bar, 1u);                                                \
        ep++;                                                                 \
        unsigned tgt = ep * (unsigned)NCTA;                                   \
        unsigned v;                                                           \
        while (1) {                                                           \
            asm volatile("ld.global.acquire.gpu.u32 %0, [%1];"                \
                         : "=r"(v) : "l"(&g_bar));                            \
            if (v >= tgt) break;                                              \
            __nanosleep(32);                                                  \
        }                                                                     \
    }                                                                         \
    __syncthreads();                                                          \
} while (0)

__global__ void __launch_bounds__(NTHR, 1) resrnn_seq(
    const float* __restrict__ h0,
    const float* __restrict__ l2b,
    const float* __restrict__ xh2hb)
{
    __shared__ float4 hs4[HD / 4];   //  8 KB: h_prev, swizzled
    __shared__ float4 sb4[H2 / 4];   // 16 KB: phase input vector, swizzled
    const int tid  = threadIdx.x;
    const int wid  = tid >> 5;
    const int lane = tid & 31;
    const int bid  = blockIdx.x;
    const int p    = bid + NCTA * wid;   // this warp's row-pair index
    unsigned  ep   = 0;

    const int pAB = (p < H2 / 2) ? p : 0;   // phases A/B: 2048 pairs
    const int pC  = (p < HD / 2) ? p : 0;   // phase C:    1024 pairs
    const uint4* qA0 = reinterpret_cast<const uint4*>(
        g_qL1h + (size_t)(2 * pAB) * HD);
    const uint4* qA1 = reinterpret_cast<const uint4*>(
        g_qL1h + (size_t)(2 * pAB + 1) * HD);
    const uint4* qB0 = reinterpret_cast<const uint4*>(
        g_qL2 + (size_t)(2 * pAB) * H2);
    const uint4* qB1 = reinterpret_cast<const uint4*>(
        g_qL2 + (size_t)(2 * pAB + 1) * H2);
    const uint4* qC0 = reinterpret_cast<const uint4*>(
        g_qXh + (size_t)(2 * pC) * H2);
    const uint4* qC1 = reinterpret_cast<const uint4*>(
        g_qXh + (size_t)(2 * pC + 1) * H2);

    // initial prefetch: phase A of step 0 (first group of each row)
    uint4 pf0 = make_uint4(0, 0, 0, 0), pf1 = pf0;
    if (p < H2 / 2) { pf0 = __ldcg(qA0 + lane); pf1 = __ldcg(qA1 + lane); }

    for (int t = 0; t < T_; t++) {
        const float4* hprev4 = (t == 0)
            ? reinterpret_cast<const float4*>(h0)
            : reinterpret_cast<const float4*>(&g_Hs[(size_t)(t - 1) * HD]);

        // ---- stage h_prev (swizzled) ----
        for (int j = tid; j < HD / 4; j += NTHR)
            hs4[j ^ ((j >> 3) & 7)] = __ldcg(hprev4 + j);
        __syncthreads();

        // ---- Phase A: z = relu(A1[t] + l1h @ h) ----
        if (p < H2 / 2) {
            float2 s = dotq_pair<HD / 8>(qA0, qA1, hs4, lane, pf0, pf1);
            if (lane == 0) {
                float2 a1 = __ldcg(reinterpret_cast<const float2*>(
                    &g_A1[(size_t)t * H2 + 2 * p]));
                const float2 sc = *reinterpret_cast<const float2*>(
                    &g_sL1h[2 * p]);
                float2 z;
                z.x = fmaxf(a1.x + sc.x * s.x, 0.f);
                z.y = fmaxf(a1.y + sc.y * s.y, 0.f);
                *reinterpret_cast<float2*>(&g_z[2 * p]) = z;
            }
        }
        // prefetch phase-B weights across the barrier
        if (p < H2 / 2) { pf0 = __ldcg(qB0 + lane); pf1 = __ldcg(qB1 + lane); }
        GRID_SYNC();

        // ---- Phase B: y2 = l2 @ z + l2_b ----
        {
            const float4* z4 = reinterpret_cast<const float4*>(g_z);
            for (int j = tid; j < H2 / 4; j += NTHR)
                sb4[j ^ ((j >> 3) & 7)] = __ldcg(z4 + j);
        }
        __syncthreads();
        if (p < H2 / 2) {
            float2 s = dotq_pair<H2 / 8>(qB0, qB1, sb4, lane, pf0, pf1);
            if (lane == 0) {
                const float2 sc = *reinterpret_cast<const float2*>(
                    &g_sL2[2 * p]);
                float2 b = __ldcg(reinterpret_cast<const float2*>(
                    l2b + 2 * p));
                float2 y;
                y.x = sc.x * s.x + b.x;
                y.y = sc.y * s.y + b.y;
                *reinterpret_cast<float2*>(&g_y2[2 * p]) = y;
            }
        }
        // prefetch phase-C weights across the barrier
        if (p < HD / 2) { pf0 = __ldcg(qC0 + lane); pf1 = __ldcg(qC1 + lane); }
        GRID_SYNC();

        // ---- Phase C: temp = relu(xh + y2); h' = xh2h @ temp + b ----
        {
            const float4* xi4 = reinterpret_cast<const float4*>(
                &g_XI[(size_t)t * HD]);
            const float4* y4 = reinterpret_cast<const float4*>(g_y2);
            for (int j = tid; j < H2 / 4; j += NTHR) {
                float4 xh;
                if (j < HD / 4) {
                    xh = __ldcg(xi4 + j);
                } else {
                    int jj = j - HD / 4;
                    xh = hs4[jj ^ ((jj >> 3) & 7)];   // unswizzle h
                }
                float4 y = __ldcg(y4 + j);
                float4 tv;
                tv.x = fmaxf(xh.x + y.x, 0.f);
                tv.y = fmaxf(xh.y + y.y, 0.f);
                tv.z = fmaxf(xh.z + y.z, 0.f);
                tv.w = fmaxf(xh.w + y.w, 0.f);
                sb4[j ^ ((j >> 3) & 7)] = tv;
            }
        }
        __syncthreads();
        if (p < HD / 2) {
            float2 s = dotq_pair<H2 / 8>(qC0, qC1, sb4, lane, pf0, pf1);
            if (lane == 0) {
                const float2 sc = *reinterpret_cast<const float2*>(
                    &g_sXh[2 * p]);
                float2 b = __ldcg(reinterpret_cast<const float2*>(
                    xh2hb + 2 * p));
                float2 h;
                h.x = sc.x * s.x + b.x;
                h.y = sc.y * s.y + b.y;
                *reinterpret_cast<float2*>(&g_Hs[(size_t)t * HD + 2 * p]) = h;
            }
        }
        // prefetch next step's phase-A weights across the barrier
        if (p < H2 / 2) { pf0 = __ldcg(qA0 + lane); pf1 = __ldcg(qA1 + lane); }
        GRID_SYNC();
    }

    // Reset barrier for next graph replay (handshake: nobody still spinning).
    if (tid == 0) {
        __threadfence();
        atomicAdd(&g_done, 1u);
        if (bid == 0) {
            unsigned v;
            while (1) {
                asm volatile("ld.global.acquire.gpu.u32 %0, [%1];"
                             : "=r"(v) : "l"(&g_done));
                if (v >= (unsigned)NCTA) break;
                __nanosleep(64);
            }
            g_bar  = 0u;
            g_done = 0u;
            __threadfence();
        }
    }
}

__global__ void copy_hfinal(float* __restrict__ out)
{
    int i = blockIdx.x * blockDim.x + threadIdx.x;
    if (i < HD) out[i] = g_Hs[(size_t)(T_ - 1) * HD + i];
}

// ---------------------------------------------------------------------------
extern "C" void kernel_launch(void* const* d_in, const int* in_sizes, int n_in,
                              void* d_out, int out_size)
{
    const float* x      = (const float*)d_in[0];
    const float* h0     = (const float*)d_in[1];
    const float* inp_w  = (const float*)d_in[2];
    const float* inp_b  = (const float*)d_in[3];
    const float* l1_w   = (const float*)d_in[4];
    const float* l1_b   = (const float*)d_in[5];
    const float* l2_w   = (const float*)d_in[6];
    const float* l2_b   = (const float*)d_in[7];
    const float* xh2h_w = (const float*)d_in[8];
    const float* xh2h_b = (const float*)d_in[9];
    const float* out_w  = (const float*)d_in[10];
    const float* out_b  = (const float*)d_in[11];

    float *pXI, *pA1, *pHs;
    cudaGetSymbolAddress((void**)&pXI, g_XI);
    cudaGetSymbolAddress((void**)&pA1, g_A1);
    cudaGetSymbolAddress((void**)&pHs, g_Hs);

    // K1: XI[512,2048] = x * inp_w^T + inp_b
    gemm_tt<<<dim3(HD / 64, T_ / 64), 256>>>(x, IND, inp_w, IND, inp_b,
                                             pXI, HD, IND);
    // K2: A1[512,4096] = XI * l1_w[:, :2048]^T + l1_b
    gemm_tt<<<dim3(H2 / 64, T_ / 64), 256>>>(pXI, HD, l1_w, H2, l1_b,
                                             pA1, H2, HD);
    // Quantize all recurrent weights in one launch
    quantize_all<<<2 * H2 + HD, 256>>>(l1_w, l2_w, xh2h_w);

    // Sequential recurrence (4th launch -> ncu -s 5 captures it)
    resrnn_seq<<<NCTA, NTHR>>>(h0, l2_b, xh2h_b);

    // K3: ys[512,1024] = Hs * out_w^T + out_b
    gemm_tt<<<dim3(OUTD / 64, T_ / 64), 256>>>(pHs, HD, out_w, HD, out_b,
                                               (float*)d_out, OUTD, HD);

    if (out_size >= T_ * OUTD + HD) {
        copy_hfinal<<<2, NTHR>>>((float*)d_out + (size_t)T_ * OUTD);
    }
}

// round 10
// speedup vs baseline: 1.3415x; 1.0985x over previous
#include <cuda_runtime.h>
#include <cstdint>

// ResRNN, int16-quantized recurrent weights, f32x2 dequant-FMA, cross-barrier
// weight prefetch, R2 grid barrier, row-pairing (R9). R10: each row-pair's
// K-dimension is split across TWO adjacent warps of the same CTA (even wid =
// low half, odd wid = high half), doubling busy warps per SMSP to hide L2
// latency; partials combined through shared memory.

#define T_    512
#define IND   1024
#define HD    2048
#define H2    4096
#define OUTD  1024
#define NCTA  148
#define NTHR  1024

typedef unsigned long long ull;

__device__ float g_XI[T_ * HD];
__device__ float g_A1[T_ * H2];
__device__ float g_Hs[T_ * HD];
__device__ float g_z [H2];
__device__ float g_y2[H2];
__device__ unsigned g_bar  = 0;
__device__ unsigned g_done = 0;

__device__ unsigned short g_qL1h[(size_t)H2 * HD];
__device__ unsigned short g_qL2 [(size_t)H2 * H2];
__device__ unsigned short g_qXh [(size_t)HD * H2];
__device__ float g_sL1h[H2];
__device__ float g_sL2 [H2];
__device__ float g_sXh [HD];

// ---------------------------------------------------------------------------
// fp32 GEMM:  C[M,N] = A[M,K] * B[N,K]^T + bias[N]   (64x64x16 tiles)
// ---------------------------------------------------------------------------
__global__ void __launch_bounds__(256) gemm_tt(
    const float* __restrict__ A, int lda,
    const float* __restrict__ B, int ldb,
    const float* __restrict__ bias,
    float* __restrict__ C, int ldc,
    int K)
{
    __shared__ float As[16][65];
    __shared__ float Bs[16][65];
    const int tx = threadIdx.x & 15;
    const int ty = threadIdx.x >> 4;
    const int m0 = blockIdx.y * 64;
    const int n0 = blockIdx.x * 64;

    float acc[4][4] = {};

    for (int k0 = 0; k0 < K; k0 += 16) {
#pragma unroll
        for (int i = threadIdx.x; i < 1024; i += 256) {
            int r  = i >> 4;
            int kk = i & 15;
            As[kk][r] = A[(size_t)(m0 + r) * lda + k0 + kk];
            Bs[kk][r] = B[(size_t)(n0 + r) * ldb + k0 + kk];
        }
        __syncthreads();
#pragma unroll
        for (int kk = 0; kk < 16; kk++) {
            float a[4], b[4];
#pragma unroll
            for (int i = 0; i < 4; i++) a[i] = As[kk][ty * 4 + i];
#pragma unroll
            for (int j = 0; j < 4; j++) b[j] = Bs[kk][tx * 4 + j];
#pragma unroll
            for (int i = 0; i < 4; i++)
#pragma unroll
                for (int j = 0; j < 4; j++)
                    acc[i][j] = fmaf(a[i], b[j], acc[i][j]);
        }
        __syncthreads();
    }

#pragma unroll
    for (int i = 0; i < 4; i++) {
        int m = m0 + ty * 4 + i;
#pragma unroll
        for (int j = 0; j < 4; j++) {
            int n = n0 + tx * 4 + j;
            C[(size_t)m * ldc + n] = acc[i][j] + bias[n];
        }
    }
}

// ---------------------------------------------------------------------------
// Merged per-row int16 quantization for all three recurrent matrices.
// ---------------------------------------------------------------------------
__global__ void __launch_bounds__(256) quantize_all(
    const float* __restrict__ l1_w,
    const float* __restrict__ l2_w,
    const float* __restrict__ xh2h_w)
{
    const int b = blockIdx.x;
    const float* src; int r, ld, col0, ncols;
    unsigned short* dst; float* scales;
    if (b < H2) {
        r = b;          src = l1_w;   ld = H2; col0 = HD; ncols = HD;
        dst = g_qL1h;   scales = g_sL1h;
    } else if (b < 2 * H2) {
        r = b - H2;     src = l2_w;   ld = H2; col0 = 0;  ncols = H2;
        dst = g_qL2;    scales = g_sL2;
    } else {
        r = b - 2 * H2; src = xh2h_w; ld = H2; col0 = 0;  ncols = H2;
        dst = g_qXh;    scales = g_sXh;
    }

    const float* row = src + (size_t)r * ld + col0;
    __shared__ float red[256];

    float m = 0.f;
    for (int i = threadIdx.x; i < ncols; i += 256)
        m = fmaxf(m, fabsf(row[i]));
    red[threadIdx.x] = m;
    __syncthreads();
    for (int s = 128; s; s >>= 1) {
        if (threadIdx.x < s)
            red[threadIdx.x] = fmaxf(red[threadIdx.x], red[threadIdx.x + s]);
        __syncthreads();
    }
    const float mx  = red[0];
    const float inv = (mx > 0.f) ? 32767.0f / mx : 0.f;
    if (threadIdx.x == 0)
        scales[r] = (mx > 0.f) ? mx / 32767.0f : 1.0f;

    unsigned short* drow = dst + (size_t)r * ncols;
    for (int i = threadIdx.x; i < ncols; i += 256) {
        int q = __float2int_rn(row[i] * inv);
        drow[i] = (unsigned short)(q + 32768);
    }
}

// ---------------------------------------------------------------------------
// f32x2 helpers
// ---------------------------------------------------------------------------
__device__ __forceinline__ ull pack2(unsigned lo, unsigned hi) {
    ull r;
    asm("mov.b64 %0, {%1, %2};" : "=l"(r) : "r"(lo), "r"(hi));
    return r;
}
__device__ __forceinline__ ull add2(ull a, ull b) {
    ull r;
    asm("add.rn.f32x2 %0, %1, %2;" : "=l"(r) : "l"(a), "l"(b));
    return r;
}
__device__ __forceinline__ ull fma2(ull a, ull b, ull c) {
    ull r;
    asm("fma.rn.f32x2 %0, %1, %2, %3;" : "=l"(r) : "l"(a), "l"(b), "l"(c));
    return r;
}

__device__ __forceinline__ float warp_red(float v) {
#pragma unroll
    for (int o = 16; o; o >>= 1) v += __shfl_down_sync(0xffffffffu, v, o);
    return v;
}

// -8421376.0f (= -(2^23 + 2^15)) in both lanes
#define NMAG2 0xCB008000CB008000ull

// dequant 2 biased-u16 (packed in u32) -> f32x2
__device__ __forceinline__ ull dq(unsigned u) {
    return add2(pack2(__byte_perm(u, 0x4B000000u, 0x7410),
                      __byte_perm(u, 0x4B000000u, 0x7432)), NMAG2);
}

// process one 16B weight group for TWO rows, sharing the x loads.
__device__ __forceinline__ void proc8p(uint4 w0, uint4 w1, int i,
                                       const ulonglong2* __restrict__ x2,
                                       ull& a00, ull& a01,
                                       ull& a10, ull& a11)
{
    int sw = (i >> 2) & 7;
    ulonglong2 X0 = x2[(2 * i) ^ sw];
    ulonglong2 X1 = x2[(2 * i) ^ sw ^ 1];
    a00 = fma2(dq(w0.x), X0.x, a00);
    a01 = fma2(dq(w0.y), X0.y, a01);
    a10 = fma2(dq(w1.x), X0.x, a10);
    a11 = fma2(dq(w1.y), X0.y, a11);
    a00 = fma2(dq(w0.z), X1.x, a00);
    a01 = fma2(dq(w0.w), X1.y, a01);
    a10 = fma2(dq(w1.z), X1.x, a10);
    a11 = fma2(dq(w1.w), X1.y, a11);
}

// half-K paired dequant-dot: rows q0,q1, NIT iterations starting at uint4
// index ioff. First group arrives prefetched.
template <int NIT>
__device__ __forceinline__ float2 dotq_ph(
    const uint4* __restrict__ q0, const uint4* __restrict__ q1,
    const float4* __restrict__ xs, int lane, int ioff,
    uint4 pf0, uint4 pf1)
{
    const ulonglong2* x2 = reinterpret_cast<const ulonglong2*>(xs);
    ull a00 = 0, a01 = 0, a10 = 0, a11 = 0;
    proc8p(pf0, pf1, ioff + lane, x2, a00, a01, a10, a11);
#pragma unroll
    for (int k = 1; k < NIT; k++) {
        int i = ioff + lane + 32 * k;
        uint4 w0 = __ldcg(q0 + i);
        uint4 w1 = __ldcg(q1 + i);
        proc8p(w0, w1, i, x2, a00, a01, a10, a11);
    }
    a00 = add2(a00, a01);
    a10 = add2(a10, a11);
    unsigned lo, hi;
    float2 s;
    asm("mov.b64 {%0, %1}, %2;" : "=r"(lo), "=r"(hi) : "l"(a00));
    s.x = warp_red(__uint_as_float(lo) + __uint_as_float(hi));
    asm("mov.b64 {%0, %1}, %2;" : "=r"(lo), "=r"(hi) : "l"(a10));
    s.y = warp_red(__uint_as_float(lo) + __uint_as_float(hi));
    return s;
}

// R2 barrier, unchanged (best measured).
#define GRID_SYNC() do {                                                      \
    __syncthreads();                                                          \
    if (tid == 0) {                                                           \
        __threadfence();                                                      \
        atomicAdd(&g_bar, 1u);                                                \
        ep++;                                                                 \
        unsigned tgt = ep * (unsigned)NCTA;                                   \
        unsigned v;                                                           \
        while (1) {                                                           \
            asm volatile("ld.global.acquire.gpu.u32 %0, [%1];"                \
                         : "=r"(v) : "l"(&g_bar));                            \
            if (v >= tgt) break;                                              \
            __nanosleep(32);                                                  \
        }                                                                     \
    }                                                                         \
    __syncthreads();                                                          \
} while (0)

__global__ void __launch_bounds__(NTHR, 1) resrnn_seq(
    const float* __restrict__ h0,
    const float* __restrict__ l2b,
    const float* __restrict__ xh2hb)
{
    __shared__ float4 hs4[HD / 4];    //  8 KB: h_prev, swizzled
    __shared__ float4 sb4[H2 / 4];    // 16 KB: phase input vector, swizzled
    __shared__ float2 spart[32];      // per-warp partial sums
    const int tid  = threadIdx.x;
    const int wid  = tid >> 5;
    const int lane = tid & 31;
    const int bid  = blockIdx.x;
    const int half = wid & 1;                   // which K-half this warp does
    const int p    = bid + NCTA * (wid >> 1);   // row-pair index
    unsigned  ep   = 0;

    const bool vAB = (p < H2 / 2);
    const bool vC  = (p < HD / 2);
    const int pAB = vAB ? p : 0;
    const int pC  = vC  ? p : 0;
    const uint4* qA0 = reinterpret_cast<const uint4*>(
        g_qL1h + (size_t)(2 * pAB) * HD);
    const uint4* qA1 = reinterpret_cast<const uint4*>(
        g_qL1h + (size_t)(2 * pAB + 1) * HD);
    const uint4* qB0 = reinterpret_cast<const uint4*>(
        g_qL2 + (size_t)(2 * pAB) * H2);
    const uint4* qB1 = reinterpret_cast<const uint4*>(
        g_qL2 + (size_t)(2 * pAB + 1) * H2);
    const uint4* qC0 = reinterpret_cast<const uint4*>(
        g_qXh + (size_t)(2 * pC) * H2);
    const uint4* qC1 = reinterpret_cast<const uint4*>(
        g_qXh + (size_t)(2 * pC + 1) * H2);

    const int ioffA  = half * (HD / 16);   // 128 uint4 per half (phase A)
    const int ioffBC = half * (H2 / 16);   // 256 uint4 per half (phases B/C)

    // initial prefetch: phase A of step 0
    uint4 pf0 = make_uint4(0, 0, 0, 0), pf1 = pf0;
    if (vAB) {
        pf0 = __ldcg(qA0 + ioffA + lane);
        pf1 = __ldcg(qA1 + ioffA + lane);
    }

    for (int t = 0; t < T_; t++) {
        const float4* hprev4 = (t == 0)
            ? reinterpret_cast<const float4*>(h0)
            : reinterpret_cast<const float4*>(&g_Hs[(size_t)(t - 1) * HD]);

        // ---- stage h_prev (swizzled) ----
        for (int j = tid; j < HD / 4; j += NTHR)
            hs4[j ^ ((j >> 3) & 7)] = __ldcg(hprev4 + j);
        __syncthreads();

        // ---- Phase A: z = relu(A1[t] + l1h @ h) ----
        if (vAB) {
            float2 s = dotq_ph<4>(qA0, qA1, hs4, lane, ioffA, pf0, pf1);
            if (lane == 0) spart[wid] = s;
        }
        if (vAB) {
            pf0 = __ldcg(qB0 + ioffBC + lane);
            pf1 = __ldcg(qB1 + ioffBC + lane);
        }
        __syncthreads();
        if (vAB && half == 0 && lane == 0) {
            float2 sa = spart[wid], sb = spart[wid + 1];
            float2 a1 = __ldcg(reinterpret_cast<const float2*>(
                &g_A1[(size_t)t * H2 + 2 * p]));
            const float2 sc = *reinterpret_cast<const float2*>(&g_sL1h[2 * p]);
            float2 z;
            z.x = fmaxf(a1.x + sc.x * (sa.x + sb.x), 0.f);
            z.y = fmaxf(a1.y + sc.y * (sa.y + sb.y), 0.f);
            *reinterpret_cast<float2*>(&g_z[2 * p]) = z;
        }
        GRID_SYNC();

        // ---- Phase B: y2 = l2 @ z + l2_b ----
        {
            const float4* z4 = reinterpret_cast<const float4*>(g_z);
            for (int j = tid; j < H2 / 4; j += NTHR)
                sb4[j ^ ((j >> 3) & 7)] = __ldcg(z4 + j);
        }
        __syncthreads();
        if (vAB) {
            float2 s = dotq_ph<8>(qB0, qB1, sb4, lane, ioffBC, pf0, pf1);
            if (lane == 0) spart[wid] = s;
        }
        if (vC) {
            pf0 = __ldcg(qC0 + ioffBC + lane);
            pf1 = __ldcg(qC1 + ioffBC + lane);
        }
        __syncthreads();
        if (vAB && half == 0 && lane == 0) {
            float2 sa = spart[wid], sb = spart[wid + 1];
            const float2 sc = *reinterpret_cast<const float2*>(&g_sL2[2 * p]);
            float2 b = __ldcg(reinterpret_cast<const float2*>(l2b + 2 * p));
            float2 y;
            y.x = sc.x * (sa.x + sb.x) + b.x;
            y.y = sc.y * (sa.y + sb.y) + b.y;
            *reinterpret_cast<float2*>(&g_y2[2 * p]) = y;
        }
        GRID_SYNC();

        // ---- Phase C: temp = relu(xh + y2); h' = xh2h @ temp + b ----
        {
            const float4* xi4 = reinterpret_cast<const float4*>(
                &g_XI[(size_t)t * HD]);
            const float4* y4 = reinterpret_cast<const float4*>(g_y2);
            for (int j = tid; j < H2 / 4; j += NTHR) {
                float4 xh;
                if (j < HD / 4) {
                    xh = __ldcg(xi4 + j);
                } else {
                    int jj = j - HD / 4;
                    xh = hs4[jj ^ ((jj >> 3) & 7)];   // unswizzle h
                }
                float4 y = __ldcg(y4 + j);
                float4 tv;
                tv.x = fmaxf(xh.x + y.x, 0.f);
                tv.y = fmaxf(xh.y + y.y, 0.f);
                tv.z = fmaxf(xh.z + y.z, 0.f);
                tv.w = fmaxf(xh.w + y.w, 0.f);
                sb4[j ^ ((j >> 3) & 7)] = tv;
            }
        }
        __syncthreads();
        if (vC) {
            float2 s = dotq_ph<8>(qC0, qC1, sb4, lane, ioffBC, pf0, pf1);
            if (lane == 0) spart[wid] = s;
        }
        if (vAB) {
            pf0 = __ldcg(qA0 + ioffA + lane);
            pf1 = __ldcg(qA1 + ioffA + lane);
        }
        __syncthreads();
        if (vC && half == 0 && lane == 0) {
            float2 sa = spart[wid], sb = spart[wid + 1];
            const float2 sc = *reinterpret_cast<const float2*>(&g_sXh[2 * p]);
            float2 b = __ldcg(reinterpret_cast<const float2*>(xh2hb + 2 * p));
            float2 h;
            h.x = sc.x * (sa.x + sb.x) + b.x;
            h.y = sc.y * (sa.y + sb.y) + b.y;
            *reinterpret_cast<float2*>(&g_Hs[(size_t)t * HD + 2 * p]) = h;
        }
        GRID_SYNC();
    }

    // Reset barrier for next graph replay (handshake: nobody still spinning).
    if (tid == 0) {
        __threadfence();
        atomicAdd(&g_done, 1u);
        if (bid == 0) {
            unsigned v;
            while (1) {
                asm volatile("ld.global.acquire.gpu.u32 %0, [%1];"
                             : "=r"(v) : "l"(&g_done));
                if (v >= (unsigned)NCTA) break;
                __nanosleep(64);
            }
            g_bar  = 0u;
            g_done = 0u;
            __threadfence();
        }
    }
}

__global__ void copy_hfinal(float* __restrict__ out)
{
    int i = blockIdx.x * blockDim.x + threadIdx.x;
    if (i < HD) out[i] = g_Hs[(size_t)(T_ - 1) * HD + i];
}

// ---------------------------------------------------------------------------
extern "C" void kernel_launch(void* const* d_in, const int* in_sizes, int n_in,
                              void* d_out, int out_size)
{
    const float* x      = (const float*)d_in[0];
    const float* h0     = (const float*)d_in[1];
    const float* inp_w  = (const float*)d_in[2];
    const float* inp_b  = (const float*)d_in[3];
    const float* l1_w   = (const float*)d_in[4];
    const float* l1_b   = (const float*)d_in[5];
    const float* l2_w   = (const float*)d_in[6];
    const float* l2_b   = (const float*)d_in[7];
    const float* xh2h_w = (const float*)d_in[8];
    const float* xh2h_b = (const float*)d_in[9];
    const float* out_w  = (const float*)d_in[10];
    const float* out_b  = (const float*)d_in[11];

    float *pXI, *pA1, *pHs;
    cudaGetSymbolAddress((void**)&pXI, g_XI);
    cudaGetSymbolAddress((void**)&pA1, g_A1);
    cudaGetSymbolAddress((void**)&pHs, g_Hs);

    // K1: XI[512,2048] = x * inp_w^T + inp_b
    gemm_tt<<<dim3(HD / 64, T_ / 64), 256>>>(x, IND, inp_w, IND, inp_b,
                                             pXI, HD, IND);
    // K2: A1[512,4096] = XI * l1_w[:, :2048]^T + l1_b
    gemm_tt<<<dim3(H2 / 64, T_ / 64), 256>>>(pXI, HD, l1_w, H2, l1_b,
                                             pA1, H2, HD);
    // Quantize all recurrent weights in one launch
    quantize_all<<<2 * H2 + HD, 256>>>(l1_w, l2_w, xh2h_w);

    // Sequential recurrence (4th launch -> ncu -s 5 captures it)
    resrnn_seq<<<NCTA, NTHR>>>(h0, l2_b, xh2h_b);

    // K3: ys[512,1024] = Hs * out_w^T + out_b
    gemm_tt<<<dim3(OUTD / 64, T_ / 64), 256>>>(pHs, HD, out_w, HD, out_b,
                                               (float*)d_out, OUTD, HD);

    if (out_size >= T_ * OUTD + HD) {
        copy_hfinal<<<2, NTHR>>>((float*)d_out + (size_t)T_ * OUTD);
    }
}